// round 1
// baseline (speedup 1.0000x reference)
#include <cuda_runtime.h>
#include <cstdint>

#define BB 2
#define LL 256
#define HH 512
#define NHH 8
#define DHH 64

// ---------------- scratch (device globals; no allocation) ----------------
__device__ float g_K[BB*LL*HH];
__device__ float g_Q[BB*LL*HH];
__device__ float g_V[BB*LL*HH];
__device__ float g_T[BB*LL*NHH*HH];   // tilde: [m][n][h], m = b*L+i   (8 MB)
__device__ float g_CTX[BB*LL*HH];

// ---------------- generic 512x512x512 fp32 GEMM body ----------------
// C[512,512] = A[512,512] @ W[512,512] + bias.  64x64 block tile, K-tile 16,
// 256 threads, 4x4 per-thread micro-tile.
__device__ __forceinline__ void gemm512_body(const float* __restrict__ A,
                                             const float* __restrict__ W,
                                             const float* __restrict__ bias,
                                             float* __restrict__ C)
{
    __shared__ __align__(16) float As[16][65];   // As[k][m] (transposed A tile)
    __shared__ __align__(16) float Bs[16][68];   // Bs[k][n]

    const int tid = threadIdx.x;
    const int tx  = tid & 15;        // 0..15  (col group)
    const int ty  = tid >> 4;        // 0..15  (row group)
    const int row0 = blockIdx.y * 64;
    const int col0 = blockIdx.x * 64;

    const int lm = tid >> 2;         // 0..63
    const int lk = (tid & 3) * 4;    // 0,4,8,12

    float acc[4][4] = {};

    for (int kt = 0; kt < 512; kt += 16) {
        // A tile: 64 rows x 16 k, loaded as float4 along k, stored transposed
        float4 a4 = *(const float4*)&A[(row0 + lm) * 512 + kt + lk];
        As[lk + 0][lm] = a4.x;
        As[lk + 1][lm] = a4.y;
        As[lk + 2][lm] = a4.z;
        As[lk + 3][lm] = a4.w;
        // W tile: 16 k x 64 n, float4 along n
        float4 b4 = *(const float4*)&W[(kt + (tid >> 4)) * 512 + col0 + (tid & 15) * 4];
        *(float4*)&Bs[tid >> 4][(tid & 15) * 4] = b4;
        __syncthreads();

        #pragma unroll
        for (int kk = 0; kk < 16; kk++) {
            float a0 = As[kk][ty * 4 + 0];
            float a1 = As[kk][ty * 4 + 1];
            float a2 = As[kk][ty * 4 + 2];
            float a3 = As[kk][ty * 4 + 3];
            float4 bv = *(const float4*)&Bs[kk][tx * 4];
            acc[0][0] += a0 * bv.x; acc[0][1] += a0 * bv.y; acc[0][2] += a0 * bv.z; acc[0][3] += a0 * bv.w;
            acc[1][0] += a1 * bv.x; acc[1][1] += a1 * bv.y; acc[1][2] += a1 * bv.z; acc[1][3] += a1 * bv.w;
            acc[2][0] += a2 * bv.x; acc[2][1] += a2 * bv.y; acc[2][2] += a2 * bv.z; acc[2][3] += a2 * bv.w;
            acc[3][0] += a3 * bv.x; acc[3][1] += a3 * bv.y; acc[3][2] += a3 * bv.z; acc[3][3] += a3 * bv.w;
        }
        __syncthreads();
    }

    #pragma unroll
    for (int r = 0; r < 4; r++) {
        int row = row0 + ty * 4 + r;
        #pragma unroll
        for (int c = 0; c < 4; c++) {
            int col = col0 + tx * 4 + c;
            C[row * 512 + col] = acc[r][c] + bias[col];
        }
    }
}

// ---------------- kernel 1: K/Q/V projections ----------------
__global__ void proj_kernel(const float* __restrict__ key,
                            const float* __restrict__ query,
                            const float* __restrict__ value,
                            const float* __restrict__ Wk, const float* __restrict__ bk,
                            const float* __restrict__ Wq, const float* __restrict__ bq,
                            const float* __restrict__ Wv, const float* __restrict__ bv)
{
    const float *A, *W, *bias;
    float* C;
    if (blockIdx.z == 0)      { A = key;   W = Wk; bias = bk; C = g_K; }
    else if (blockIdx.z == 1) { A = query; W = Wq; bias = bq; C = g_Q; }
    else                      { A = value; W = Wv; bias = bv; C = g_V; }
    gemm512_body(A, W, bias, C);
}

// ---------------- kernel 2: tilde ----------------
// T[m][n][h] = sum_d (Q[m, n*64+d] + vpos[n*64+d]) * Wr[h, n*64+d]
// Per head n: GEMM  M=512 (m), N=512 (h), K=64 (d).
__global__ void tilde_kernel(const float* __restrict__ Wr,
                             const float* __restrict__ vpos)
{
    __shared__ float As[16][65];   // As[d][m]
    __shared__ float Bs[16][65];   // Bs[d][h]

    const int tid = threadIdx.x;
    const int tx = tid & 15, ty = tid >> 4;
    const int h0 = blockIdx.x * 64;
    const int m0 = blockIdx.y * 64;
    const int n  = blockIdx.z;

    const int lm = tid >> 2;         // 0..63
    const int lk = (tid & 3) * 4;    // 0,4,8,12

    float acc[4][4] = {};

    for (int kt = 0; kt < DHH; kt += 16) {
        float4 a4 = *(const float4*)&g_Q[(m0 + lm) * HH + n * DHH + kt + lk];
        float4 vb = *(const float4*)&vpos[n * DHH + kt + lk];
        a4.x += vb.x; a4.y += vb.y; a4.z += vb.z; a4.w += vb.w;
        As[lk + 0][lm] = a4.x;
        As[lk + 1][lm] = a4.y;
        As[lk + 2][lm] = a4.z;
        As[lk + 3][lm] = a4.w;
        // Wr accessed transposed: Bs[d][h] = Wr[h0+lm][n*64+kt+lk..]
        float4 b4 = *(const float4*)&Wr[(h0 + lm) * HH + n * DHH + kt + lk];
        Bs[lk + 0][lm] = b4.x;
        Bs[lk + 1][lm] = b4.y;
        Bs[lk + 2][lm] = b4.z;
        Bs[lk + 3][lm] = b4.w;
        __syncthreads();

        #pragma unroll
        for (int kk = 0; kk < 16; kk++) {
            float a0 = As[kk][ty * 4 + 0];
            float a1 = As[kk][ty * 4 + 1];
            float a2 = As[kk][ty * 4 + 2];
            float a3 = As[kk][ty * 4 + 3];
            float b0 = Bs[kk][tx * 4 + 0];
            float b1 = Bs[kk][tx * 4 + 1];
            float b2 = Bs[kk][tx * 4 + 2];
            float b3 = Bs[kk][tx * 4 + 3];
            acc[0][0] += a0 * b0; acc[0][1] += a0 * b1; acc[0][2] += a0 * b2; acc[0][3] += a0 * b3;
            acc[1][0] += a1 * b0; acc[1][1] += a1 * b1; acc[1][2] += a1 * b2; acc[1][3] += a1 * b3;
            acc[2][0] += a2 * b0; acc[2][1] += a2 * b1; acc[2][2] += a2 * b2; acc[2][3] += a2 * b3;
            acc[3][0] += a3 * b0; acc[3][1] += a3 * b1; acc[3][2] += a3 * b2; acc[3][3] += a3 * b3;
        }
        __syncthreads();
    }

    #pragma unroll
    for (int r = 0; r < 4; r++) {
        int m = m0 + ty * 4 + r;
        #pragma unroll
        for (int c = 0; c < 4; c++)
            g_T[((size_t)m * NHH + n) * HH + h0 + tx * 4 + c] = acc[r][c];
    }
}

// ---------------- kernel 3: fused attention per (b,i) ----------------
// scores[n][j] = ( (q+u)_n . k_j,n  +  sum_h rpe[b,i,j,h] T[m][n][h] ) / 8, masked,
// softmax over j, then ctx[n,d] = sum_j p[n][j] V[b,j,n*64+d].
__global__ void attn_kernel(const float* __restrict__ rpe,
                            const int* __restrict__ seq_len,
                            const int* __restrict__ lex_num,
                            const float* __restrict__ upos)
{
    __shared__ __align__(16) float sW[NHH * HH];   // T rows for this (b,i): 16 KB
    __shared__ __align__(16) float qu[HH];         // flattened q+u: 2 KB
    __shared__ float ss[NHH * 257];                // scores/probs, padded
    __shared__ int s_limit;

    const int tid  = threadIdx.x;
    const int m    = blockIdx.x;          // b*L + i
    const int b    = m >> 8;              // L = 256
    const int lane = tid & 31;
    const int w    = tid >> 5;            // warp id, 0..7

    for (int idx = tid; idx < NHH * HH; idx += 256)
        sW[idx] = g_T[(size_t)m * NHH * HH + idx];
    for (int idx = tid; idx < HH; idx += 256)
        qu[idx] = g_Q[m * HH + idx] + upos[idx];
    if (tid == 0) s_limit = seq_len[b] + lex_num[0];
    __syncthreads();

    const int limit = s_limit;
    const float4* sW4 = (const float4*)sW;
    const float4* qu4 = (const float4*)qu;

    // ---- phase 1: scores (warp w handles j = jt*8 + w) ----
    for (int jt = 0; jt < LL / 8; jt++) {
        const int j = jt * 8 + w;
        const float4* rpe4 = (const float4*)(rpe + ((size_t)m * LL + j) * HH);
        const float4* k4   = (const float4*)(g_K + (size_t)(b * LL + j) * HH);

        float acc[8] = {0.f,0.f,0.f,0.f,0.f,0.f,0.f,0.f};
        #pragma unroll
        for (int it = 0; it < 4; it++) {
            const int off = lane + 32 * it;       // float4 index within 512-float row
            float4 r  = rpe4[off];
            float4 kv = k4[off];
            float4 q4 = qu4[off];
            // AC contribution: this float4 covers head (off*4)/64 = 2*it + (lane>=16)
            float kd = kv.x*q4.x + kv.y*q4.y + kv.z*q4.z + kv.w*q4.w;
            if (lane < 16) acc[2*it]     += kd;
            else           acc[2*it + 1] += kd;
            // BD contribution: all 8 heads
            #pragma unroll
            for (int n = 0; n < 8; n++) {
                float4 wv = sW4[n * (HH / 4) + off];
                acc[n] += r.x*wv.x + r.y*wv.y + r.z*wv.z + r.w*wv.w;
            }
        }
        // warp reduce all 8 heads
        #pragma unroll
        for (int n = 0; n < 8; n++) {
            #pragma unroll
            for (int o = 16; o; o >>= 1)
                acc[n] += __shfl_xor_sync(0xffffffffu, acc[n], o);
        }
        float val = acc[0];
        #pragma unroll
        for (int n = 1; n < 8; n++)
            if (lane == n) val = acc[n];
        if (lane < 8)
            ss[lane * 257 + j] = (j < limit) ? val * 0.125f : -1e15f;
    }
    __syncthreads();

    // ---- phase 2: softmax, warp w owns head w ----
    {
        float vals[8];
        #pragma unroll
        for (int t = 0; t < 8; t++) vals[t] = ss[w * 257 + lane + 32 * t];
        float mx = vals[0];
        #pragma unroll
        for (int t = 1; t < 8; t++) mx = fmaxf(mx, vals[t]);
        #pragma unroll
        for (int o = 16; o; o >>= 1) mx = fmaxf(mx, __shfl_xor_sync(0xffffffffu, mx, o));
        float sum = 0.f;
        #pragma unroll
        for (int t = 0; t < 8; t++) { vals[t] = __expf(vals[t] - mx); sum += vals[t]; }
        #pragma unroll
        for (int o = 16; o; o >>= 1) sum += __shfl_xor_sync(0xffffffffu, sum, o);
        float inv = 1.f / sum;
        #pragma unroll
        for (int t = 0; t < 8; t++) ss[w * 257 + lane + 32 * t] = vals[t] * inv;
    }
    __syncthreads();

    // ---- phase 3: ctx[h] = sum_j p[h/64][j] * V[b,j,h]; thread owns h=tid and tid+256 ----
    {
        const int h0 = tid, h1 = tid + 256;
        const int hd0 = h0 >> 6, hd1 = h1 >> 6;
        const float* Vb = g_V + (size_t)b * LL * HH;
        float o0 = 0.f, o1 = 0.f;
        #pragma unroll 4
        for (int j = 0; j < LL; j++) {
            float p0 = ss[hd0 * 257 + j];
            float p1 = ss[hd1 * 257 + j];
            o0 += p0 * Vb[j * HH + h0];
            o1 += p1 * Vb[j * HH + h1];
        }
        g_CTX[m * HH + h0] = o0;
        g_CTX[m * HH + h1] = o1;
    }
}

// ---------------- kernel 4: output projection ----------------
__global__ void final_kernel(const float* __restrict__ Wf,
                             const float* __restrict__ bf,
                             float* __restrict__ out)
{
    gemm512_body(g_CTX, Wf, bf, out);
}

// ---------------- launch ----------------
extern "C" void kernel_launch(void* const* d_in, const int* in_sizes, int n_in,
                              void* d_out, int out_size)
{
    const float* key     = (const float*)d_in[0];
    const float* query   = (const float*)d_in[1];
    const float* value   = (const float*)d_in[2];
    const int*   seq_len = (const int*)  d_in[3];
    const int*   lex_num = (const int*)  d_in[4];
    // d_in[5] pos_s, d_in[6] pos_e: unused by the reference math
    const float* rpe     = (const float*)d_in[7];
    const float* Wk      = (const float*)d_in[8];
    const float* bk      = (const float*)d_in[9];
    const float* Wq      = (const float*)d_in[10];
    const float* bq      = (const float*)d_in[11];
    const float* Wv      = (const float*)d_in[12];
    const float* bv      = (const float*)d_in[13];
    const float* Wr      = (const float*)d_in[14];
    // d_in[15] br: its BD contribution is constant over j -> softmax-invariant -> dropped
    const float* upos    = (const float*)d_in[16];
    const float* vpos    = (const float*)d_in[17];
    const float* Wf      = (const float*)d_in[18];
    const float* bf      = (const float*)d_in[19];
    float* out = (float*)d_out;

    proj_kernel <<<dim3(8, 8, 3), 256>>>(key, query, value, Wk, bk, Wq, bq, Wv, bv);
    tilde_kernel<<<dim3(8, 8, 8), 256>>>(Wr, vpos);
    attn_kernel <<<dim3(BB * LL), 256>>>(rpe, seq_len, lex_num, upos);
    final_kernel<<<dim3(8, 8), 256>>>(Wf, bf, out);
}

// round 3
// speedup vs baseline: 1.8299x; 1.8299x over previous
#include <cuda_runtime.h>
#include <cstdint>

#define BB 2
#define LL 256
#define HH 512
#define NHH 8
#define DHH 64

// ---------------- scratch (device globals; no allocation) ----------------
__device__ __align__(16) float g_K[BB*LL*HH];
__device__ __align__(16) float g_Q[BB*LL*HH];
__device__ __align__(16) float g_V[BB*LL*HH];
__device__ __align__(16) float g_T[BB*LL*NHH*HH];    // [m][n][h]  8 MB
__device__ __align__(16) float g_AC[BB*LL*NHH*LL];   // [m][n][j]  4 MB
__device__ __align__(16) float g_P[BB*LL*NHH*LL];    // [m][n][j]  4 MB
__device__ __align__(16) float g_CTX[BB*LL*HH];

// ---------------- f32x2 helpers ----------------
__device__ __forceinline__ unsigned long long ffma2(unsigned long long a,
                                                    unsigned long long b,
                                                    unsigned long long c) {
    unsigned long long d;
    asm("fma.rn.f32x2 %0, %1, %2, %3;" : "=l"(d) : "l"(a), "l"(b), "l"(c));
    return d;
}
__device__ __forceinline__ unsigned long long splat2(float a) {
    unsigned long long r;
    asm("mov.b64 %0, {%1, %1};" : "=l"(r) : "f"(a));
    return r;
}
__device__ __forceinline__ float2 unpack2(unsigned long long v) {
    float2 f;
    asm("mov.b64 {%0, %1}, %2;" : "=f"(f.x), "=f"(f.y) : "l"(v));
    return f;
}
__device__ __forceinline__ void cpasync16(uint32_t s, const void* g) {
    asm volatile("cp.async.cg.shared.global [%0], [%1], 16;\n" :: "r"(s), "l"(g));
}
__device__ __forceinline__ void cpasync_commit() {
    asm volatile("cp.async.commit_group;\n" ::: "memory");
}
template <int N>
__device__ __forceinline__ void cpasync_wait() {
    asm volatile("cp.async.wait_group %0;\n" :: "n"(N) : "memory");
}

// ---------------- 512x512x512 GEMM, k-tile 32, reg double-buffer, FMA2 ----------------
__device__ __forceinline__ void gemm512_body(const float* __restrict__ A,
                                             const float* __restrict__ W,
                                             const float* __restrict__ bias,
                                             float* __restrict__ C)
{
    __shared__ __align__(16) float As[32][68];
    __shared__ __align__(16) float Bs[32][68];

    const int tid = threadIdx.x;
    const int tx  = tid & 15;
    const int ty  = tid >> 4;
    const int row0 = blockIdx.y * 64;
    const int col0 = blockIdx.x * 64;

    const int lm = tid >> 2;          // A row within tile
    const int lk = (tid & 3) * 4;     // A k offset
    const int wr = tid >> 4;          // W row pair base
    const int wc = (tid & 15) * 4;    // W col offset

    float4 a0 = *(const float4*)&A[(row0 + lm) * 512 + 0  + lk];
    float4 a1 = *(const float4*)&A[(row0 + lm) * 512 + 16 + lk];
    float4 b0 = *(const float4*)&W[(0  + wr) * 512 + col0 + wc];
    float4 b1 = *(const float4*)&W[(16 + wr) * 512 + col0 + wc];

    unsigned long long acc[4][2] = {};

    for (int kt = 0; kt < 512; kt += 32) {
        As[lk + 0][lm] = a0.x; As[lk + 1][lm] = a0.y;
        As[lk + 2][lm] = a0.z; As[lk + 3][lm] = a0.w;
        As[16 + lk + 0][lm] = a1.x; As[16 + lk + 1][lm] = a1.y;
        As[16 + lk + 2][lm] = a1.z; As[16 + lk + 3][lm] = a1.w;
        *(float4*)&Bs[wr][wc]      = b0;
        *(float4*)&Bs[wr + 16][wc] = b1;
        __syncthreads();

        if (kt + 32 < 512) {
            a0 = *(const float4*)&A[(row0 + lm) * 512 + kt + 32 + lk];
            a1 = *(const float4*)&A[(row0 + lm) * 512 + kt + 48 + lk];
            b0 = *(const float4*)&W[(kt + 32 + wr) * 512 + col0 + wc];
            b1 = *(const float4*)&W[(kt + 48 + wr) * 512 + col0 + wc];
        }

        #pragma unroll
        for (int kk = 0; kk < 32; kk++) {
            float4 av = *(const float4*)&As[kk][ty * 4];
            ulonglong2 bp = *(const ulonglong2*)&Bs[kk][tx * 4];
            unsigned long long s0 = splat2(av.x);
            unsigned long long s1 = splat2(av.y);
            unsigned long long s2 = splat2(av.z);
            unsigned long long s3 = splat2(av.w);
            acc[0][0] = ffma2(s0, bp.x, acc[0][0]); acc[0][1] = ffma2(s0, bp.y, acc[0][1]);
            acc[1][0] = ffma2(s1, bp.x, acc[1][0]); acc[1][1] = ffma2(s1, bp.y, acc[1][1]);
            acc[2][0] = ffma2(s2, bp.x, acc[2][0]); acc[2][1] = ffma2(s2, bp.y, acc[2][1]);
            acc[3][0] = ffma2(s3, bp.x, acc[3][0]); acc[3][1] = ffma2(s3, bp.y, acc[3][1]);
        }
        __syncthreads();
    }

    float4 bb = *(const float4*)&bias[col0 + tx * 4];
    #pragma unroll
    for (int r = 0; r < 4; r++) {
        float2 p0 = unpack2(acc[r][0]);
        float2 p1 = unpack2(acc[r][1]);
        float4 o;
        o.x = p0.x + bb.x; o.y = p0.y + bb.y;
        o.z = p1.x + bb.z; o.w = p1.y + bb.w;
        *(float4*)&C[(row0 + ty * 4 + r) * 512 + col0 + tx * 4] = o;
    }
}

__global__ void proj_kernel(const float* __restrict__ key,
                            const float* __restrict__ query,
                            const float* __restrict__ value,
                            const float* __restrict__ Wk, const float* __restrict__ bk,
                            const float* __restrict__ Wq, const float* __restrict__ bq,
                            const float* __restrict__ Wv, const float* __restrict__ bv)
{
    const float *A, *W, *bias;
    float* C;
    if (blockIdx.z == 0)      { A = key;   W = Wk; bias = bk; C = g_K; }
    else if (blockIdx.z == 1) { A = query; W = Wq; bias = bq; C = g_Q; }
    else                      { A = value; W = Wv; bias = bv; C = g_V; }
    gemm512_body(A, W, bias, C);
}

__global__ void final_kernel(const float* __restrict__ Wf,
                             const float* __restrict__ bf,
                             float* __restrict__ out)
{
    gemm512_body(g_CTX, Wf, bf, out);
}

// ---------------- K=64 A@B^T body (tilde + AC) ----------------
// C[i][c] = sum_d (A[i*512+d] + avec[d]) * B[c*512+d],  i,c in [0,64)
__device__ __forceinline__ void nt64_body(const float* __restrict__ Arow0,
                                          const float* __restrict__ avec,
                                          const float* __restrict__ Brow0,
                                          float* __restrict__ Cbase, int ldc)
{
    __shared__ __align__(16) float As[16][68];
    __shared__ __align__(16) float Bs[16][68];

    const int tid = threadIdx.x;
    const int tx = tid & 15, ty = tid >> 4;
    const int lm = tid >> 2;
    const int lk = (tid & 3) * 4;

    unsigned long long acc[4][2] = {};

    for (int kt = 0; kt < 64; kt += 16) {
        float4 a4 = *(const float4*)&Arow0[lm * 512 + kt + lk];
        float4 vb = *(const float4*)&avec[kt + lk];
        a4.x += vb.x; a4.y += vb.y; a4.z += vb.z; a4.w += vb.w;
        As[lk + 0][lm] = a4.x; As[lk + 1][lm] = a4.y;
        As[lk + 2][lm] = a4.z; As[lk + 3][lm] = a4.w;
        float4 b4 = *(const float4*)&Brow0[lm * 512 + kt + lk];
        Bs[lk + 0][lm] = b4.x; Bs[lk + 1][lm] = b4.y;
        Bs[lk + 2][lm] = b4.z; Bs[lk + 3][lm] = b4.w;
        __syncthreads();

        #pragma unroll
        for (int kk = 0; kk < 16; kk++) {
            float4 av = *(const float4*)&As[kk][ty * 4];
            ulonglong2 bp = *(const ulonglong2*)&Bs[kk][tx * 4];
            unsigned long long s0 = splat2(av.x);
            unsigned long long s1 = splat2(av.y);
            unsigned long long s2 = splat2(av.z);
            unsigned long long s3 = splat2(av.w);
            acc[0][0] = ffma2(s0, bp.x, acc[0][0]); acc[0][1] = ffma2(s0, bp.y, acc[0][1]);
            acc[1][0] = ffma2(s1, bp.x, acc[1][0]); acc[1][1] = ffma2(s1, bp.y, acc[1][1]);
            acc[2][0] = ffma2(s2, bp.x, acc[2][0]); acc[2][1] = ffma2(s2, bp.y, acc[2][1]);
            acc[3][0] = ffma2(s3, bp.x, acc[3][0]); acc[3][1] = ffma2(s3, bp.y, acc[3][1]);
        }
        __syncthreads();
    }

    #pragma unroll
    for (int r = 0; r < 4; r++) {
        float2 p0 = unpack2(acc[r][0]);
        float2 p1 = unpack2(acc[r][1]);
        float4 o; o.x = p0.x; o.y = p0.y; o.z = p1.x; o.w = p1.y;
        *(float4*)&Cbase[(ty * 4 + r) * ldc + tx * 4] = o;
    }
}

// tilde: T[m][n][h] = sum_d (Q[m][n*64+d]+vpos[n*64+d]) * Wr[h][n*64+d]
__global__ void tilde_kernel(const float* __restrict__ Wr,
                             const float* __restrict__ vpos)
{
    const int h0 = blockIdx.x * 64;
    const int m0 = blockIdx.y * 64;
    const int n  = blockIdx.z;
    nt64_body(g_Q + m0 * 512 + n * 64, vpos + n * 64,
              Wr + h0 * 512 + n * 64,
              g_T + (m0 * 8 + n) * 512 + h0, 4096);
}

// AC: AC[m][n][j] = sum_d (Q[m][n*64+d]+upos[n*64+d]) * K[b][j][n*64+d]
__global__ void ac_kernel(const float* __restrict__ upos)
{
    const int j0 = blockIdx.x * 64;
    const int b  = blockIdx.y >> 2;
    const int i0 = (blockIdx.y & 3) * 64;
    const int n  = blockIdx.z;
    nt64_body(g_Q + (b * 256 + i0) * 512 + n * 64, upos + n * 64,
              g_K + (b * 256 + j0) * 512 + n * 64,
              g_AC + ((b * 256 + i0) * 8 + n) * 256 + j0, 2048);
}

// ---------------- attn: scores + softmax -> P ----------------
// per block m: S[n][j] = AC[m][n][j] + sum_h rpe[m,j,h]*T[m,n,h], scaled+masked,
// softmax over j, write P.
// dyn smem floats: rpe_s 2*32*516 | T_s 8*512 | red 8*32*9 | ss 8*260
#define RPE_STRIDE 516
#define RPE_BUF    (32 * RPE_STRIDE)       // 16512
#define OFF_T      (2 * RPE_BUF)           // 33024
#define OFF_RED    (OFF_T + 4096)          // 37120
#define OFF_SS     (OFF_RED + 2304)        // 39424
#define ATTN_SMEM  ((OFF_SS + 2080) * 4)   // 166016 bytes

__device__ __forceinline__ void attn_load_chunk(float* dst, const float* src, int tid)
{
    const int jj = tid >> 3;       // 0..31
    const int f0 = tid & 7;        // 0..7
    const float4* g = (const float4*)src + (size_t)jj * 128;
    uint32_t s = (uint32_t)__cvta_generic_to_shared(dst + jj * RPE_STRIDE);
    #pragma unroll
    for (int t = 0; t < 16; t++)
        cpasync16(s + (f0 + t * 8) * 16, g + f0 + t * 8);
}

__global__ __launch_bounds__(256, 1)
void attn_kernel(const float* __restrict__ rpe,
                 const int* __restrict__ seq_len,
                 const int* __restrict__ lex_num)
{
    extern __shared__ __align__(16) float smem[];
    float* rpe_s = smem;
    float* T_s   = smem + OFF_T;
    float* red   = smem + OFF_RED;
    float* ss    = smem + OFF_SS;
    __shared__ int s_limit;

    const int tid  = threadIdx.x;
    const int m    = blockIdx.x;
    const int b    = m >> 8;
    const int w    = tid >> 5;      // warp = h-part (compute) / head (softmax)
    const int lane = tid & 31;

    const float* rpe_m = rpe + (size_t)m * 256 * 512;

    // prefetch chunk 0 ASAP
    attn_load_chunk(rpe_s, rpe_m, tid);
    cpasync_commit();

    // T rows for this m
    {
        const float4* src = (const float4*)(g_T + (size_t)m * 4096);
        float4* dst = (float4*)T_s;
        #pragma unroll
        for (int t = 0; t < 4; t++)
            dst[tid + 256 * t] = src[tid + 256 * t];
    }
    if (tid == 0) s_limit = seq_len[b] + lex_num[0];
    __syncthreads();
    const int limit = s_limit;

    for (int c = 0; c < 8; c++) {
        const int j0 = c * 32;
        if (c < 7) {
            attn_load_chunk(rpe_s + ((c + 1) & 1) * RPE_BUF,
                            rpe_m + (size_t)(j0 + 32) * 512, tid);
            cpasync_commit();
            cpasync_wait<1>();
        } else {
            cpasync_wait<0>();
        }
        __syncthreads();

        // compute: warp w covers h in [w*64, w*64+64), lane = j within chunk
        {
            const float* rrow = rpe_s + ((c & 1) * RPE_BUF) + lane * RPE_STRIDE + w * 64;
            const float* trow = T_s + w * 64;
            unsigned long long acc[8] = {};
            #pragma unroll
            for (int s4 = 0; s4 < 16; s4++) {
                ulonglong2 r = *(const ulonglong2*)(rrow + s4 * 4);
                #pragma unroll
                for (int n = 0; n < 8; n++) {
                    ulonglong2 t = *(const ulonglong2*)(trow + n * 512 + s4 * 4);
                    acc[n] = ffma2(r.x, t.x, acc[n]);
                    acc[n] = ffma2(r.y, t.y, acc[n]);
                }
            }
            #pragma unroll
            for (int n = 0; n < 8; n++) {
                float2 f = unpack2(acc[n]);
                red[w * 288 + lane * 9 + n] = f.x + f.y;
            }
        }
        __syncthreads();

        // reduce over h-parts, add AC, scale+mask
        {
            const int n2 = tid >> 5;
            const int jj = tid & 31;
            float v = 0.f;
            #pragma unroll
            for (int p = 0; p < 8; p++)
                v += red[p * 288 + jj * 9 + n2];
            v += g_AC[((size_t)m * 8 + n2) * 256 + j0 + jj];
            ss[n2 * 260 + j0 + jj] = (j0 + jj < limit) ? v * 0.125f : -1e15f;
        }
        __syncthreads();
    }

    // softmax: warp w = head w
    {
        float vals[8];
        #pragma unroll
        for (int t = 0; t < 8; t++) vals[t] = ss[w * 260 + lane + 32 * t];
        float mx = vals[0];
        #pragma unroll
        for (int t = 1; t < 8; t++) mx = fmaxf(mx, vals[t]);
        #pragma unroll
        for (int o = 16; o; o >>= 1) mx = fmaxf(mx, __shfl_xor_sync(0xffffffffu, mx, o));
        float sum = 0.f;
        #pragma unroll
        for (int t = 0; t < 8; t++) { vals[t] = __expf(vals[t] - mx); sum += vals[t]; }
        #pragma unroll
        for (int o = 16; o; o >>= 1) sum += __shfl_xor_sync(0xffffffffu, sum, o);
        float inv = 1.f / sum;
        #pragma unroll
        for (int t = 0; t < 8; t++) ss[w * 260 + lane + 32 * t] = vals[t] * inv;
    }
    __syncthreads();

    // write P
    {
        float4* P4 = (float4*)g_P + (size_t)m * 512;
        #pragma unroll
        for (int t = 0; t < 2; t++) {
            int f = tid + 256 * t;          // float4 index, 0..511
            int n = f >> 6;
            int c4 = f & 63;
            P4[f] = *(const float4*)&ss[n * 260 + c4 * 4];
        }
    }
}

// ---------------- ctx: CTX[m][n*64+d] = sum_j P[m][n][j] * V[b][j][n*64+d] ----------------
__global__ void ctx_kernel()
{
    __shared__ __align__(16) float Ps[64][68];   // [j][i] transposed
    __shared__ __align__(16) float Vs[64][68];   // [j][d]

    const int tid = threadIdx.x;
    const int tx = tid & 15, ty = tid >> 4;
    const int i0 = blockIdx.x * 64;
    const int n  = blockIdx.y;
    const int b  = blockIdx.z;

    unsigned long long acc[4][2] = {};

    for (int j0 = 0; j0 < 256; j0 += 64) {
        // P tile: 64 i-rows x 64 j, transposed store.
        // Each thread loads 4 float4s to cover the full 64-wide j extent.
        {
            const int li = tid >> 2;               // i within tile, 0..63
            #pragma unroll
            for (int q = 0; q < 4; q++) {
                int jf = (tid & 3) + q * 4;        // float4 index 0..15 within row
                float4 p4 = *(const float4*)&g_P[(((size_t)(b * 256 + i0 + li)) * 8 + n) * 256 + j0 + jf * 4];
                Ps[jf * 4 + 0][li] = p4.x;
                Ps[jf * 4 + 1][li] = p4.y;
                Ps[jf * 4 + 2][li] = p4.z;
                Ps[jf * 4 + 3][li] = p4.w;
            }
        }
        // V tile: 64 j-rows x 64 d
        {
            const int lj = tid >> 2;
            const int fl = tid & 3;
            #pragma unroll
            for (int q = 0; q < 4; q++) {
                int f4 = fl + q * 4;
                float4 v4 = *(const float4*)&g_V[(size_t)(b * 256 + j0 + lj) * 512 + n * 64 + f4 * 4];
                *(float4*)&Vs[lj][f4 * 4] = v4;
            }
        }
        __syncthreads();

        #pragma unroll 16
        for (int j = 0; j < 64; j++) {
            float4 av = *(const float4*)&Ps[j][ty * 4];
            ulonglong2 bp = *(const ulonglong2*)&Vs[j][tx * 4];
            unsigned long long s0 = splat2(av.x);
            unsigned long long s1 = splat2(av.y);
            unsigned long long s2 = splat2(av.z);
            unsigned long long s3 = splat2(av.w);
            acc[0][0] = ffma2(s0, bp.x, acc[0][0]); acc[0][1] = ffma2(s0, bp.y, acc[0][1]);
            acc[1][0] = ffma2(s1, bp.x, acc[1][0]); acc[1][1] = ffma2(s1, bp.y, acc[1][1]);
            acc[2][0] = ffma2(s2, bp.x, acc[2][0]); acc[2][1] = ffma2(s2, bp.y, acc[2][1]);
            acc[3][0] = ffma2(s3, bp.x, acc[3][0]); acc[3][1] = ffma2(s3, bp.y, acc[3][1]);
        }
        __syncthreads();
    }

    #pragma unroll
    for (int r = 0; r < 4; r++) {
        float2 p0 = unpack2(acc[r][0]);
        float2 p1 = unpack2(acc[r][1]);
        float4 o; o.x = p0.x; o.y = p0.y; o.z = p1.x; o.w = p1.y;
        *(float4*)&g_CTX[(size_t)(b * 256 + i0 + ty * 4 + r) * 512 + n * 64 + tx * 4] = o;
    }
}

// ---------------- launch ----------------
extern "C" void kernel_launch(void* const* d_in, const int* in_sizes, int n_in,
                              void* d_out, int out_size)
{
    const float* key     = (const float*)d_in[0];
    const float* query   = (const float*)d_in[1];
    const float* value   = (const float*)d_in[2];
    const int*   seq_len = (const int*)  d_in[3];
    const int*   lex_num = (const int*)  d_in[4];
    const float* rpe     = (const float*)d_in[7];
    const float* Wk      = (const float*)d_in[8];
    const float* bk      = (const float*)d_in[9];
    const float* Wq      = (const float*)d_in[10];
    const float* bq      = (const float*)d_in[11];
    const float* Wv      = (const float*)d_in[12];
    const float* bv      = (const float*)d_in[13];
    const float* Wr      = (const float*)d_in[14];
    const float* upos    = (const float*)d_in[16];
    const float* vpos    = (const float*)d_in[17];
    const float* Wf      = (const float*)d_in[18];
    const float* bf      = (const float*)d_in[19];
    float* out = (float*)d_out;

    static bool attr_set = false;
    if (!attr_set) {
        cudaFuncSetAttribute(attn_kernel,
                             cudaFuncAttributeMaxDynamicSharedMemorySize, ATTN_SMEM);
        attr_set = true;
    }

    proj_kernel <<<dim3(8, 8, 3), 256>>>(key, query, value, Wk, bk, Wq, bq, Wv, bv);
    tilde_kernel<<<dim3(8, 8, 8), 256>>>(Wr, vpos);
    ac_kernel   <<<dim3(4, 8, 8), 256>>>(upos);
    attn_kernel <<<dim3(BB * LL), 256, ATTN_SMEM>>>(rpe, seq_len, lex_num);
    ctx_kernel  <<<dim3(4, 8, 2), 256>>>();
    final_kernel<<<dim3(8, 8), 256>>>(Wf, bf, out);
}

// round 4
// speedup vs baseline: 1.9582x; 1.0701x over previous
#include <cuda_runtime.h>
#include <cstdint>

#define BB 2
#define LL 256
#define HH 512
#define NHH 8
#define DHH 64

// ---------------- scratch (device globals; no allocation) ----------------
__device__ __align__(16) float g_K[BB*LL*HH];
__device__ __align__(16) float g_Q[BB*LL*HH];
__device__ __align__(16) float g_V[BB*LL*HH];
__device__ __align__(16) float g_T[BB*LL*NHH*HH];    // [m][n][h]  8 MB
__device__ __align__(16) float g_AC[BB*LL*NHH*LL];   // [m][n][j]  4 MB
__device__ __align__(16) float g_P[BB*LL*NHH*LL];    // [m][n][j]  4 MB
__device__ __align__(16) float g_CTX[BB*LL*HH];

// ---------------- f32x2 helpers ----------------
__device__ __forceinline__ unsigned long long ffma2(unsigned long long a,
                                                    unsigned long long b,
                                                    unsigned long long c) {
    unsigned long long d;
    asm("fma.rn.f32x2 %0, %1, %2, %3;" : "=l"(d) : "l"(a), "l"(b), "l"(c));
    return d;
}
__device__ __forceinline__ unsigned long long splat2(float a) {
    unsigned long long r;
    asm("mov.b64 %0, {%1, %1};" : "=l"(r) : "f"(a));
    return r;
}
__device__ __forceinline__ float2 unpack2(unsigned long long v) {
    float2 f;
    asm("mov.b64 {%0, %1}, %2;" : "=f"(f.x), "=f"(f.y) : "l"(v));
    return f;
}
__device__ __forceinline__ void cpasync16(uint32_t s, const void* g) {
    asm volatile("cp.async.cg.shared.global [%0], [%1], 16;\n" :: "r"(s), "l"(g));
}
__device__ __forceinline__ void cpasync_commit() {
    asm volatile("cp.async.commit_group;\n" ::: "memory");
}
template <int N>
__device__ __forceinline__ void cpasync_wait() {
    asm volatile("cp.async.wait_group %0;\n" :: "n"(N) : "memory");
}

// ---------------- 512x512x512 GEMM, k-tile 32, reg double-buffer, FMA2 ----------------
__device__ __forceinline__ void gemm512_body(const float* __restrict__ A,
                                             const float* __restrict__ W,
                                             const float* __restrict__ bias,
                                             float* __restrict__ C)
{
    __shared__ __align__(16) float As[32][68];
    __shared__ __align__(16) float Bs[32][68];

    const int tid = threadIdx.x;
    const int tx  = tid & 15;
    const int ty  = tid >> 4;
    const int row0 = blockIdx.y * 64;
    const int col0 = blockIdx.x * 64;

    const int lm = tid >> 2;          // A row within tile
    const int lk = (tid & 3) * 4;     // A k offset
    const int wr = tid >> 4;          // W row pair base
    const int wc = (tid & 15) * 4;    // W col offset

    float4 a0 = *(const float4*)&A[(row0 + lm) * 512 + 0  + lk];
    float4 a1 = *(const float4*)&A[(row0 + lm) * 512 + 16 + lk];
    float4 b0 = *(const float4*)&W[(0  + wr) * 512 + col0 + wc];
    float4 b1 = *(const float4*)&W[(16 + wr) * 512 + col0 + wc];

    unsigned long long acc[4][2] = {};

    for (int kt = 0; kt < 512; kt += 32) {
        As[lk + 0][lm] = a0.x; As[lk + 1][lm] = a0.y;
        As[lk + 2][lm] = a0.z; As[lk + 3][lm] = a0.w;
        As[16 + lk + 0][lm] = a1.x; As[16 + lk + 1][lm] = a1.y;
        As[16 + lk + 2][lm] = a1.z; As[16 + lk + 3][lm] = a1.w;
        *(float4*)&Bs[wr][wc]      = b0;
        *(float4*)&Bs[wr + 16][wc] = b1;
        __syncthreads();

        if (kt + 32 < 512) {
            a0 = *(const float4*)&A[(row0 + lm) * 512 + kt + 32 + lk];
            a1 = *(const float4*)&A[(row0 + lm) * 512 + kt + 48 + lk];
            b0 = *(const float4*)&W[(kt + 32 + wr) * 512 + col0 + wc];
            b1 = *(const float4*)&W[(kt + 48 + wr) * 512 + col0 + wc];
        }

        #pragma unroll
        for (int kk = 0; kk < 32; kk++) {
            float4 av = *(const float4*)&As[kk][ty * 4];
            ulonglong2 bp = *(const ulonglong2*)&Bs[kk][tx * 4];
            unsigned long long s0 = splat2(av.x);
            unsigned long long s1 = splat2(av.y);
            unsigned long long s2 = splat2(av.z);
            unsigned long long s3 = splat2(av.w);
            acc[0][0] = ffma2(s0, bp.x, acc[0][0]); acc[0][1] = ffma2(s0, bp.y, acc[0][1]);
            acc[1][0] = ffma2(s1, bp.x, acc[1][0]); acc[1][1] = ffma2(s1, bp.y, acc[1][1]);
            acc[2][0] = ffma2(s2, bp.x, acc[2][0]); acc[2][1] = ffma2(s2, bp.y, acc[2][1]);
            acc[3][0] = ffma2(s3, bp.x, acc[3][0]); acc[3][1] = ffma2(s3, bp.y, acc[3][1]);
        }
        __syncthreads();
    }

    float4 bb = *(const float4*)&bias[col0 + tx * 4];
    #pragma unroll
    for (int r = 0; r < 4; r++) {
        float2 p0 = unpack2(acc[r][0]);
        float2 p1 = unpack2(acc[r][1]);
        float4 o;
        o.x = p0.x + bb.x; o.y = p0.y + bb.y;
        o.z = p1.x + bb.z; o.w = p1.y + bb.w;
        *(float4*)&C[(row0 + ty * 4 + r) * 512 + col0 + tx * 4] = o;
    }
}

__global__ void proj_kernel(const float* __restrict__ key,
                            const float* __restrict__ query,
                            const float* __restrict__ value,
                            const float* __restrict__ Wk, const float* __restrict__ bk,
                            const float* __restrict__ Wq, const float* __restrict__ bq,
                            const float* __restrict__ Wv, const float* __restrict__ bv)
{
    const float *A, *W, *bias;
    float* C;
    if (blockIdx.z == 0)      { A = key;   W = Wk; bias = bk; C = g_K; }
    else if (blockIdx.z == 1) { A = query; W = Wq; bias = bq; C = g_Q; }
    else                      { A = value; W = Wv; bias = bv; C = g_V; }
    gemm512_body(A, W, bias, C);
}

__global__ void final_kernel(const float* __restrict__ Wf,
                             const float* __restrict__ bf,
                             float* __restrict__ out)
{
    gemm512_body(g_CTX, Wf, bf, out);
}

// ---------------- K=64 A@B^T body (tilde + AC) ----------------
// C[i][c] = sum_d (A[i*512+d] + avec[d]) * B[c*512+d],  i,c in [0,64)
__device__ __forceinline__ void nt64_body(const float* __restrict__ Arow0,
                                          const float* __restrict__ avec,
                                          const float* __restrict__ Brow0,
                                          float* __restrict__ Cbase, int ldc)
{
    __shared__ __align__(16) float As[16][68];
    __shared__ __align__(16) float Bs[16][68];

    const int tid = threadIdx.x;
    const int tx = tid & 15, ty = tid >> 4;
    const int lm = tid >> 2;
    const int lk = (tid & 3) * 4;

    unsigned long long acc[4][2] = {};

    for (int kt = 0; kt < 64; kt += 16) {
        float4 a4 = *(const float4*)&Arow0[lm * 512 + kt + lk];
        float4 vb = *(const float4*)&avec[kt + lk];
        a4.x += vb.x; a4.y += vb.y; a4.z += vb.z; a4.w += vb.w;
        As[lk + 0][lm] = a4.x; As[lk + 1][lm] = a4.y;
        As[lk + 2][lm] = a4.z; As[lk + 3][lm] = a4.w;
        float4 b4 = *(const float4*)&Brow0[lm * 512 + kt + lk];
        Bs[lk + 0][lm] = b4.x; Bs[lk + 1][lm] = b4.y;
        Bs[lk + 2][lm] = b4.z; Bs[lk + 3][lm] = b4.w;
        __syncthreads();

        #pragma unroll
        for (int kk = 0; kk < 16; kk++) {
            float4 av = *(const float4*)&As[kk][ty * 4];
            ulonglong2 bp = *(const ulonglong2*)&Bs[kk][tx * 4];
            unsigned long long s0 = splat2(av.x);
            unsigned long long s1 = splat2(av.y);
            unsigned long long s2 = splat2(av.z);
            unsigned long long s3 = splat2(av.w);
            acc[0][0] = ffma2(s0, bp.x, acc[0][0]); acc[0][1] = ffma2(s0, bp.y, acc[0][1]);
            acc[1][0] = ffma2(s1, bp.x, acc[1][0]); acc[1][1] = ffma2(s1, bp.y, acc[1][1]);
            acc[2][0] = ffma2(s2, bp.x, acc[2][0]); acc[2][1] = ffma2(s2, bp.y, acc[2][1]);
            acc[3][0] = ffma2(s3, bp.x, acc[3][0]); acc[3][1] = ffma2(s3, bp.y, acc[3][1]);
        }
        __syncthreads();
    }

    #pragma unroll
    for (int r = 0; r < 4; r++) {
        float2 p0 = unpack2(acc[r][0]);
        float2 p1 = unpack2(acc[r][1]);
        float4 o; o.x = p0.x; o.y = p0.y; o.z = p1.x; o.w = p1.y;
        *(float4*)&Cbase[(ty * 4 + r) * ldc + tx * 4] = o;
    }
}

// tilde: T[m][n][h] = sum_d (Q[m][n*64+d]+vpos[n*64+d]) * Wr[h][n*64+d]
__global__ void tilde_kernel(const float* __restrict__ Wr,
                             const float* __restrict__ vpos)
{
    const int h0 = blockIdx.x * 64;
    const int m0 = blockIdx.y * 64;
    const int n  = blockIdx.z;
    nt64_body(g_Q + m0 * 512 + n * 64, vpos + n * 64,
              Wr + h0 * 512 + n * 64,
              g_T + (m0 * 8 + n) * 512 + h0, 4096);
}

// AC: AC[m][n][j] = sum_d (Q[m][n*64+d]+upos[n*64+d]) * K[b][j][n*64+d]
__global__ void ac_kernel(const float* __restrict__ upos)
{
    const int j0 = blockIdx.x * 64;
    const int b  = blockIdx.y >> 2;
    const int i0 = (blockIdx.y & 3) * 64;
    const int n  = blockIdx.z;
    nt64_body(g_Q + (b * 256 + i0) * 512 + n * 64, upos + n * 64,
              g_K + (b * 256 + j0) * 512 + n * 64,
              g_AC + ((b * 256 + i0) * 8 + n) * 256 + j0, 2048);
}

// ---------------- attn: scores + softmax -> P ----------------
// per block m: S[n][j] = AC[m][n][j] + sum_h rpe[m,j,h]*T[m,n,h], scaled+masked,
// softmax over j, write P.
// chunk = 16 j; 2 CTAs/SM.
// dyn smem floats: rpe_s 2*16*516 | T_s 8*512 | red 16*16*9 | ss 8*260
#define CHUNK      16
#define RPE_STRIDE 516
#define RPE_BUF    (CHUNK * RPE_STRIDE)    // 8256
#define OFF_T      (2 * RPE_BUF)           // 16512
#define OFF_RED    (OFF_T + 4096)          // 20608
#define OFF_SS     (OFF_RED + 2304)        // 22912
#define ATTN_SMEM  ((OFF_SS + 2080) * 4)   // 99968 bytes

__device__ __forceinline__ void attn_load_chunk(float* dst, const float* src, int tid)
{
    // 16 rows x 512 floats = 2048 float4; 256 threads x 8 float4
    const int jj = tid >> 4;       // 0..15
    const int f0 = tid & 15;       // 0..15
    const float4* g = (const float4*)src + (size_t)jj * 128;
    uint32_t s = (uint32_t)__cvta_generic_to_shared(dst + jj * RPE_STRIDE);
    #pragma unroll
    for (int t = 0; t < 8; t++)
        cpasync16(s + (f0 + t * 16) * 16, g + f0 + t * 16);
}

__global__ __launch_bounds__(256, 2)
void attn_kernel(const float* __restrict__ rpe,
                 const int* __restrict__ seq_len,
                 const int* __restrict__ lex_num)
{
    extern __shared__ __align__(16) float smem[];
    float* rpe_s = smem;
    float* T_s   = smem + OFF_T;
    float* red   = smem + OFF_RED;
    float* ss    = smem + OFF_SS;
    __shared__ int s_limit;

    const int tid  = threadIdx.x;
    const int m    = blockIdx.x;
    const int b    = m >> 8;
    const int w    = tid >> 5;      // warp: h-window (compute) / head (softmax)
    const int lane = tid & 31;

    const float* rpe_m = rpe + (size_t)m * 256 * 512;

    // prefetch chunk 0 ASAP
    attn_load_chunk(rpe_s, rpe_m, tid);
    cpasync_commit();

    // T rows for this m
    {
        const float4* src = (const float4*)(g_T + (size_t)m * 4096);
        float4* dst = (float4*)T_s;
        #pragma unroll
        for (int t = 0; t < 4; t++)
            dst[tid + 256 * t] = src[tid + 256 * t];
    }
    if (tid == 0) s_limit = seq_len[b] + lex_num[0];
    __syncthreads();
    const int limit = s_limit;

    // lane mapping inside compute: jj = lane&15 (j in chunk), hh = lane>>4 (h half)
    const int jj_c = lane & 15;
    const int hh   = lane >> 4;
    const int part = w * 2 + hh;           // 0..15

    for (int c = 0; c < 16; c++) {
        const int j0 = c * CHUNK;
        if (c < 15) {
            attn_load_chunk(rpe_s + ((c + 1) & 1) * RPE_BUF,
                            rpe_m + (size_t)(j0 + CHUNK) * 512, tid);
            cpasync_commit();
            cpasync_wait<1>();
        } else {
            cpasync_wait<0>();
        }
        __syncthreads();

        // compute: part covers h in [w*64 + hh*32, +32), lane's j = jj_c
        {
            const float* rrow = rpe_s + ((c & 1) * RPE_BUF) + jj_c * RPE_STRIDE + w * 64 + hh * 32;
            const float* trow = T_s + w * 64 + hh * 32;
            unsigned long long acc[8] = {};
            #pragma unroll
            for (int s4 = 0; s4 < 8; s4++) {
                ulonglong2 r = *(const ulonglong2*)(rrow + s4 * 4);
                #pragma unroll
                for (int n = 0; n < 8; n++) {
                    ulonglong2 t = *(const ulonglong2*)(trow + n * 512 + s4 * 4);
                    acc[n] = ffma2(r.x, t.x, acc[n]);
                    acc[n] = ffma2(r.y, t.y, acc[n]);
                }
            }
            #pragma unroll
            for (int n = 0; n < 8; n++) {
                float2 f = unpack2(acc[n]);
                red[part * 144 + jj_c * 9 + n] = f.x + f.y;
            }
        }
        __syncthreads();

        // reduce over 16 parts, add AC, scale+mask (128 threads)
        if (tid < 128) {
            const int n2 = tid >> 4;
            const int jr = tid & 15;
            float v = 0.f;
            #pragma unroll
            for (int p = 0; p < 16; p++)
                v += red[p * 144 + jr * 9 + n2];
            v += g_AC[((size_t)m * 8 + n2) * 256 + j0 + jr];
            ss[n2 * 260 + j0 + jr] = (j0 + jr < limit) ? v * 0.125f : -1e15f;
        }
        __syncthreads();
    }

    // softmax: warp w = head w
    {
        float vals[8];
        #pragma unroll
        for (int t = 0; t < 8; t++) vals[t] = ss[w * 260 + lane + 32 * t];
        float mx = vals[0];
        #pragma unroll
        for (int t = 1; t < 8; t++) mx = fmaxf(mx, vals[t]);
        #pragma unroll
        for (int o = 16; o; o >>= 1) mx = fmaxf(mx, __shfl_xor_sync(0xffffffffu, mx, o));
        float sum = 0.f;
        #pragma unroll
        for (int t = 0; t < 8; t++) { vals[t] = __expf(vals[t] - mx); sum += vals[t]; }
        #pragma unroll
        for (int o = 16; o; o >>= 1) sum += __shfl_xor_sync(0xffffffffu, sum, o);
        float inv = 1.f / sum;
        #pragma unroll
        for (int t = 0; t < 8; t++) ss[w * 260 + lane + 32 * t] = vals[t] * inv;
    }
    __syncthreads();

    // write P
    {
        float4* P4 = (float4*)g_P + (size_t)m * 512;
        #pragma unroll
        for (int t = 0; t < 2; t++) {
            int f = tid + 256 * t;          // float4 index, 0..511
            int n = f >> 6;
            int c4 = f & 63;
            P4[f] = *(const float4*)&ss[n * 260 + c4 * 4];
        }
    }
}

// ---------------- ctx: CTX[m][n*64+d] = sum_j P[m][n][j] * V[b][j][n*64+d] ----------------
__global__ void ctx_kernel()
{
    __shared__ __align__(16) float Ps[64][68];   // [j][i] transposed
    __shared__ __align__(16) float Vs[64][68];   // [j][d]

    const int tid = threadIdx.x;
    const int tx = tid & 15, ty = tid >> 4;
    const int i0 = blockIdx.x * 64;
    const int n  = blockIdx.y;
    const int b  = blockIdx.z;

    unsigned long long acc[4][2] = {};

    for (int j0 = 0; j0 < 256; j0 += 64) {
        // P tile: 64 i-rows x 64 j, transposed store.
        {
            const int li = tid >> 2;               // i within tile, 0..63
            #pragma unroll
            for (int q = 0; q < 4; q++) {
                int jf = (tid & 3) + q * 4;        // float4 index 0..15 within row
                float4 p4 = *(const float4*)&g_P[(((size_t)(b * 256 + i0 + li)) * 8 + n) * 256 + j0 + jf * 4];
                Ps[jf * 4 + 0][li] = p4.x;
                Ps[jf * 4 + 1][li] = p4.y;
                Ps[jf * 4 + 2][li] = p4.z;
                Ps[jf * 4 + 3][li] = p4.w;
            }
        }
        // V tile: 64 j-rows x 64 d
        {
            const int lj = tid >> 2;
            const int fl = tid & 3;
            #pragma unroll
            for (int q = 0; q < 4; q++) {
                int f4 = fl + q * 4;
                float4 v4 = *(const float4*)&g_V[(size_t)(b * 256 + j0 + lj) * 512 + n * 64 + f4 * 4];
                *(float4*)&Vs[lj][f4 * 4] = v4;
            }
        }
        __syncthreads();

        #pragma unroll 16
        for (int j = 0; j < 64; j++) {
            float4 av = *(const float4*)&Ps[j][ty * 4];
            ulonglong2 bp = *(const ulonglong2*)&Vs[j][tx * 4];
            unsigned long long s0 = splat2(av.x);
            unsigned long long s1 = splat2(av.y);
            unsigned long long s2 = splat2(av.z);
            unsigned long long s3 = splat2(av.w);
            acc[0][0] = ffma2(s0, bp.x, acc[0][0]); acc[0][1] = ffma2(s0, bp.y, acc[0][1]);
            acc[1][0] = ffma2(s1, bp.x, acc[1][0]); acc[1][1] = ffma2(s1, bp.y, acc[1][1]);
            acc[2][0] = ffma2(s2, bp.x, acc[2][0]); acc[2][1] = ffma2(s2, bp.y, acc[2][1]);
            acc[3][0] = ffma2(s3, bp.x, acc[3][0]); acc[3][1] = ffma2(s3, bp.y, acc[3][1]);
        }
        __syncthreads();
    }

    #pragma unroll
    for (int r = 0; r < 4; r++) {
        float2 p0 = unpack2(acc[r][0]);
        float2 p1 = unpack2(acc[r][1]);
        float4 o; o.x = p0.x; o.y = p0.y; o.z = p1.x; o.w = p1.y;
        *(float4*)&g_CTX[(size_t)(b * 256 + i0 + ty * 4 + r) * 512 + n * 64 + tx * 4] = o;
    }
}

// ---------------- launch ----------------
extern "C" void kernel_launch(void* const* d_in, const int* in_sizes, int n_in,
                              void* d_out, int out_size)
{
    const float* key     = (const float*)d_in[0];
    const float* query   = (const float*)d_in[1];
    const float* value   = (const float*)d_in[2];
    const int*   seq_len = (const int*)  d_in[3];
    const int*   lex_num = (const int*)  d_in[4];
    const float* rpe     = (const float*)d_in[7];
    const float* Wk      = (const float*)d_in[8];
    const float* bk      = (const float*)d_in[9];
    const float* Wq      = (const float*)d_in[10];
    const float* bq      = (const float*)d_in[11];
    const float* Wv      = (const float*)d_in[12];
    const float* bv      = (const float*)d_in[13];
    const float* Wr      = (const float*)d_in[14];
    const float* upos    = (const float*)d_in[16];
    const float* vpos    = (const float*)d_in[17];
    const float* Wf      = (const float*)d_in[18];
    const float* bf      = (const float*)d_in[19];
    float* out = (float*)d_out;

    static bool attr_set = false;
    if (!attr_set) {
        cudaFuncSetAttribute(attn_kernel,
                             cudaFuncAttributeMaxDynamicSharedMemorySize, ATTN_SMEM);
        attr_set = true;
    }

    proj_kernel <<<dim3(8, 8, 3), 256>>>(key, query, value, Wk, bk, Wq, bq, Wv, bv);
    tilde_kernel<<<dim3(8, 8, 8), 256>>>(Wr, vpos);
    ac_kernel   <<<dim3(4, 8, 8), 256>>>(upos);
    attn_kernel <<<dim3(BB * LL), 256, ATTN_SMEM>>>(rpe, seq_len, lex_num);
    ctx_kernel  <<<dim3(4, 8, 2), 256>>>();
    final_kernel<<<dim3(8, 8), 256>>>(Wf, bf, out);
}